// round 16
// baseline (speedup 1.0000x reference)
#include <cuda_runtime.h>

// RNN_33964601377372: h_{t+1} = relu(x_t*W_ih + b_ih + b_hh + W_hh h_t), out = fc(h_T)
//
// Scalar L=8 row-split + SHUFFLE exchange at uniform 2 warps/SMSP.
// Session model: wall = max(n_warps x slots, ~214 latency floor); shuffle
// kernels run at 100% issue (R1/R2), smem exchange pays ~+80 cyc RAW stall
// (R13/14), f32x2 is throughput-neutral (rt-4 effective). This config is the
// only cell with 2 warps/SMSP AND slots < 107: per lane 63 scalar FFMA
// (3 rows x 21; lanes e>=4 carry a dummy duplicate of row e) + 20 width-8
// shuffles + 3 FMNMX ~ 89 slots -> wall ~ 2x89 = 178 cyc/step.
// block=256 (8 warps -> exactly 2/SMSP), grid=128 -> 1 CTA/SM, 4 batches/warp.

#define HID 20

__global__ __launch_bounds__(256) void rnn_fused_kernel(
    const float* __restrict__ x,    // [B, T]
    const float* __restrict__ Wih,  // [H]
    const float* __restrict__ Whh,  // [H, H] row-major
    const float* __restrict__ bih,  // [H]
    const float* __restrict__ bhh,  // [H]
    const float* __restrict__ fcw,  // [H]
    const float* __restrict__ fcb,  // [1]
    float* __restrict__ out,        // [B]
    int B, int T)
{
    const int lt = threadIdx.x;
    const int g  = lt >> 3;            // batch within CTA (0..31)
    const int e  = lt & 7;             // lane within 8-lane batch group
    int batch = blockIdx.x * 32 + g;
    const bool real = (batch < B);
    if (!real) batch = B - 1;          // clamp; lane must stay for shuffles

    // Owned rows: slot0=row e, slot1=row 8+e, slot2=row 16+e (e<4) else dummy
    // duplicate of row e (same weights -> same value; never read via shuffle).
    const int r_[3] = { e, 8 + e, (e < 4) ? 16 + e : e };

    // Scalar weight slices (registers, fully unrolled).
    float w0[HID], w1[HID], w2[HID];
#pragma unroll
    for (int j = 0; j < HID; ++j) {
        w0[j] = Whh[r_[0] * HID + j];
        w1[j] = Whh[r_[1] * HID + j];
        w2[j] = Whh[r_[2] * HID + j];
    }
    const float wih0 = Wih[r_[0]], wih1 = Wih[r_[1]], wih2 = Wih[r_[2]];
    const float b0 = bih[r_[0]] + bhh[r_[0]];
    const float b1 = bih[r_[1]] + bhh[r_[1]];
    const float b2 = bih[r_[2]] + bhh[r_[2]];

    float h[3] = {0.0f, 0.0f, 0.0f};

    const float* xb = x + (size_t)batch * T;   // 4000B stride, 16B-aligned;
    const float4* xb4 = (const float4*)xb;     // 8 lanes share addr (L1 bcast)
    const int nChunks = T >> 2;

    auto step = [&](float xt) {
        float acc0 = fmaf(xt, wih0, b0);
        float acc1 = fmaf(xt, wih1, b1);
        float acc2 = fmaf(xt, wih2, b2);
#pragma unroll
        for (int j = 0; j < HID; ++j) {
            // h_j lives in reg slot (j>>3) of group-lane (j&7); consts after
            // unroll -> plain SHFL.IDX width 8.
            float hj = __shfl_sync(0xffffffffu, h[j >> 3], j & 7, 8);
            acc0 = fmaf(hj, w0[j], acc0);
            acc1 = fmaf(hj, w1[j], acc1);
            acc2 = fmaf(hj, w2[j], acc2);
        }
        h[0] = fmaxf(acc0, 0.0f);
        h[1] = fmaxf(acc1, 0.0f);
        h[2] = fmaxf(acc2, 0.0f);
    };

    // Deep x prefetch: 2 chunks (8 steps) in flight.
    float4 x0 = make_float4(0.f, 0.f, 0.f, 0.f);
    float4 x1 = x0;
    if (nChunks > 0) x0 = xb4[0];
    if (nChunks > 1) x1 = xb4[1];

    for (int c = 0; c < nChunks; ++c) {
        float4 x2 = x1;
        if (c + 2 < nChunks) x2 = xb4[c + 2];
        step(x0.x);
        step(x0.y);
        step(x0.z);
        step(x0.w);
        x0 = x1;
        x1 = x2;
    }
    for (int t = nChunks << 2; t < T; ++t) step(xb[t]);  // tail (unused @T=1000)

    // Head: out[b] = h . fc_w + fc_b over owned rows (dummy masked), then
    // xor-reduce across the 8-lane group.
    float p = h[0] * fcw[r_[0]] + h[1] * fcw[r_[1]];
    if (e < 4) p += h[2] * fcw[r_[2]];
    p += __shfl_xor_sync(0xffffffffu, p, 1, 8);
    p += __shfl_xor_sync(0xffffffffu, p, 2, 8);
    p += __shfl_xor_sync(0xffffffffu, p, 4, 8);
    if (e == 0 && real) out[batch] = p + fcb[0];
}

extern "C" void kernel_launch(void* const* d_in, const int* in_sizes, int n_in,
                              void* d_out, int out_size)
{
    const float* x    = (const float*)d_in[0];
    const float* Wih  = (const float*)d_in[1];
    const float* Whh  = (const float*)d_in[2];
    const float* bih  = (const float*)d_in[3];
    const float* bhh  = (const float*)d_in[4];
    const float* fcw  = (const float*)d_in[5];
    const float* fcb  = (const float*)d_in[6];
    float* out = (float*)d_out;

    int B = out_size;
    int T = in_sizes[0] / B;

    const int threads = 256;            // 8 warps -> exactly 2 per SMSP
    int blocks = (B + 31) / 32;         // 32 batches/CTA -> 128 CTAs at B=4096
    rnn_fused_kernel<<<blocks, threads>>>(x, Wih, Whh, bih, bhh, fcw, fcb, out, B, T);
}

// round 17
// speedup vs baseline: 1.1600x; 1.1600x over previous
#include <cuda_runtime.h>

// RNN_33964601377372: h_{t+1} = relu(x_t*W_ih + b_ih + b_hh + W_hh h_t), out = fc(h_T)
//
// j-packed FFMA2 quad with PAIR-SHUFFLE exchange. Lane q of each 4-lane quad
// owns rows {2q, 2q+1, 8+2q, 9+2q, 16+q}: its first four h values pack into
// exactly two j-pairs (Pa, Pb), so the per-step exchange is 8 u64 shuffles
// (16 SHFL) + 4 scalar SHFL + 2 packs — 20 MIO ops, ZERO dup/pack-MOV chains
// (R4/R6's failure mode). Each row's 10-pair dot product = two 6-deep FFMA2
// chains + FADD2 (latency-capped). Per warp-step: ~65 fma ops, 20 MIO, ~10 alu.
// Walls: fma ~130, MIO 4w x 20 x 1.75 = 140, chain ~110.
// block=128, grid=128: 1 CTA/SM, 1 warp/SMSP, uniform.

#define HID 20
#define QUAD 4

typedef unsigned long long u64;

__device__ __forceinline__ u64 pack2(float lo, float hi) {
    u64 r; asm("mov.b64 %0, {%1, %2};" : "=l"(r) : "f"(lo), "f"(hi)); return r;
}
__device__ __forceinline__ u64 dup2(float v) {
    u64 r; asm("mov.b64 %0, {%1, %1};" : "=l"(r) : "f"(v)); return r;
}
__device__ __forceinline__ void unpack2(u64 p, float& lo, float& hi) {
    asm("mov.b64 {%0, %1}, %2;" : "=f"(lo), "=f"(hi) : "l"(p));
}
__device__ __forceinline__ u64 ffma2(u64 a, u64 b, u64 c) {
    u64 d; asm("fma.rn.f32x2 %0, %1, %2, %3;" : "=l"(d) : "l"(a), "l"(b), "l"(c)); return d;
}
__device__ __forceinline__ u64 fmul2(u64 a, u64 b) {
    u64 d; asm("mul.rn.f32x2 %0, %1, %2;" : "=l"(d) : "l"(a), "l"(b)); return d;
}
__device__ __forceinline__ u64 fadd2(u64 a, u64 b) {
    u64 d; asm("add.rn.f32x2 %0, %1, %2;" : "=l"(d) : "l"(a), "l"(b)); return d;
}

__global__ __launch_bounds__(128) void rnn_fused_kernel(
    const float* __restrict__ x,    // [B, T]
    const float* __restrict__ Wih,  // [H]
    const float* __restrict__ Whh,  // [H, H] row-major
    const float* __restrict__ bih,  // [H]
    const float* __restrict__ bhh,  // [H]
    const float* __restrict__ fcw,  // [H]
    const float* __restrict__ fcb,  // [1]
    float* __restrict__ out,        // [B]
    int B, int T)
{
    int tid = blockIdx.x * blockDim.x + threadIdx.x;
    int batch = tid >> 2;
    int q = tid & 3;               // lane within quad
    if (batch >= B) return;        // whole quad exits together (4 lanes/batch)

    // Permuted row ownership: first 4 rows form two natural j-pairs.
    const int rows[5] = { 2 * q, 2 * q + 1, 8 + 2 * q, 9 + 2 * q, 16 + q };

    // j-packed weights: wJ[r][k] = (Whh[row_r][2k], Whh[row_r][2k+1])
    u64 wJ[5][10];
#pragma unroll
    for (int r = 0; r < 5; ++r)
#pragma unroll
        for (int k = 0; k < 10; ++k)
            wJ[r][k] = pack2(Whh[rows[r] * HID + 2 * k],
                             Whh[rows[r] * HID + 2 * k + 1]);

    // x-projection + bias folded into chain-A seed (lo half).
    u64 wihP[5], biasP[5];
#pragma unroll
    for (int r = 0; r < 5; ++r) {
        wihP[r]  = pack2(Wih[rows[r]], 0.0f);
        biasP[r] = pack2(bih[rows[r]] + bhh[rows[r]], 0.0f);
    }

    // State: Pa = (h_{2q}, h_{2q+1}) = j-pair q ; Pb = (h_{8+2q}, h_{9+2q}) =
    // j-pair 4+q ; h4 = h_{16+q} (rows 16..19 pair up across lanes).
    u64 Pa = 0, Pb = 0;
    float h4 = 0.0f;

    const float* xb = x + (size_t)batch * T;   // 4000B stride, 16B-aligned
    const float4* xb4 = (const float4*)xb;
    const int nChunks = T >> 2;

    auto step = [&](float xt) {
        // Exchange: j-pairs 0..3 = Pa of lanes 0..3; 4..7 = Pb of lanes 0..3;
        // 8 = (h4@0, h4@1); 9 = (h4@2, h4@3). 16+4 SHFL + 2 packs, no dups.
        u64 hp[10];
#pragma unroll
        for (int k = 0; k < 4; ++k)
            hp[k] = __shfl_sync(0xffffffffu, Pa, k, QUAD);
#pragma unroll
        for (int k = 0; k < 4; ++k)
            hp[4 + k] = __shfl_sync(0xffffffffu, Pb, k, QUAD);
        {
            float s16 = __shfl_sync(0xffffffffu, h4, 0, QUAD);
            float s17 = __shfl_sync(0xffffffffu, h4, 1, QUAD);
            float s18 = __shfl_sync(0xffffffffu, h4, 2, QUAD);
            float s19 = __shfl_sync(0xffffffffu, h4, 3, QUAD);
            hp[8] = pack2(s16, s17);
            hp[9] = pack2(s18, s19);
        }

        u64 xt2 = dup2(xt);
        u64 accA[5], accB[5];
#pragma unroll
        for (int r = 0; r < 5; ++r)
            accA[r] = ffma2(xt2, wihP[r], biasP[r]);   // independent seeds
#pragma unroll
        for (int r = 0; r < 5; ++r)
            accB[r] = fmul2(hp[5], wJ[r][5]);
#pragma unroll
        for (int k = 0; k < 5; ++k)
#pragma unroll
            for (int r = 0; r < 5; ++r)
                accA[r] = ffma2(hp[k], wJ[r][k], accA[r]);
#pragma unroll
        for (int k = 6; k < 10; ++k)
#pragma unroll
            for (int r = 0; r < 5; ++r)
                accB[r] = ffma2(hp[k], wJ[r][k], accB[r]);

        float hn[5];
#pragma unroll
        for (int r = 0; r < 5; ++r) {
            u64 s = fadd2(accA[r], accB[r]);
            float lo, hi;
            unpack2(s, lo, hi);
            hn[r] = fmaxf(lo + hi, 0.0f);
        }
        Pa = pack2(hn[0], hn[1]);
        Pb = pack2(hn[2], hn[3]);
        h4 = hn[4];
    };

    // Deep x prefetch: 2 chunks (8 steps) in flight.
    float4 x0 = make_float4(0.f, 0.f, 0.f, 0.f);
    float4 x1 = x0;
    if (nChunks > 0) x0 = xb4[0];
    if (nChunks > 1) x1 = xb4[1];

    for (int c = 0; c < nChunks; ++c) {
        float4 x2 = x1;
        if (c + 2 < nChunks) x2 = xb4[c + 2];
        step(x0.x);
        step(x0.y);
        step(x0.z);
        step(x0.w);
        x0 = x1;
        x1 = x2;
    }
    for (int t = nChunks << 2; t < T; ++t) step(xb[t]);  // tail (unused @T=1000)

    // Head: out[b] = h . fc_w + fc_b over my permuted rows, quad butterfly.
    float a0, a1, b0v, b1v;
    unpack2(Pa, a0, a1);
    unpack2(Pb, b0v, b1v);
    float p = a0 * fcw[rows[0]] + a1 * fcw[rows[1]]
            + b0v * fcw[rows[2]] + b1v * fcw[rows[3]]
            + h4 * fcw[rows[4]];
    p += __shfl_xor_sync(0xffffffffu, p, 1, QUAD);
    p += __shfl_xor_sync(0xffffffffu, p, 2, QUAD);
    if (q == 0) out[batch] = p + fcb[0];
}

extern "C" void kernel_launch(void* const* d_in, const int* in_sizes, int n_in,
                              void* d_out, int out_size)
{
    const float* x    = (const float*)d_in[0];
    const float* Wih  = (const float*)d_in[1];
    const float* Whh  = (const float*)d_in[2];
    const float* bih  = (const float*)d_in[3];
    const float* bhh  = (const float*)d_in[4];
    const float* fcw  = (const float*)d_in[5];
    const float* fcb  = (const float*)d_in[6];
    float* out = (float*)d_out;

    int B = out_size;
    int T = in_sizes[0] / B;

    const int threads = 128;              // 4 warps -> 1 per SMSP; 32 batches/CTA
    int total = B * QUAD;                 // 16384 lanes
    int blocks = (total + threads - 1) / threads;   // 128 CTAs at B=4096
    rnn_fused_kernel<<<blocks, threads>>>(x, Wih, Whh, bih, bhh, fcw, fcb, out, B, T);
}